// round 1
// baseline (speedup 1.0000x reference)
#include <cuda_runtime.h>
#include <cstdint>

// ---------------------------------------------------------------------------
// Problem constants
// ---------------------------------------------------------------------------
#define H_HEADS 8
#define CH      640
#define HC      5120           // H_HEADS * CH
#define NS      4096
#define NSEC    512
#define NEG_SLOPE 0.2f

// ---------------------------------------------------------------------------
// Scratch pool (static device allocations only; no cudaMalloc anywhere)
// ---------------------------------------------------------------------------
constexpr size_t SZ_NODE  = (size_t)NS * HC;       // 20,971,520 floats
constexpr size_t SZ_SEC   = (size_t)NSEC * HC;     //  2,621,440
constexpr size_t SZ_FFN   = (size_t)NS * 640;      //  2,621,440
constexpr size_t SZ_AL    = (size_t)NS * H_HEADS;  //     32,768
constexpr size_t SZ_ALSEC = (size_t)NSEC * H_HEADS;//      4,096

constexpr size_t OF_HSW  = 0;                      // word-src projection (rows 0..4095)
constexpr size_t OF_HDW  = OF_HSW  + SZ_NODE;
constexpr size_t OF_HSS  = OF_HDW  + SZ_NODE;      // sentence projection (src+dst)
constexpr size_t OF_HDS  = OF_HSS  + SZ_NODE;      // section-gat dst projection
constexpr size_t OF_HSEC = OF_HDS  + SZ_NODE;      // section src projection
constexpr size_t OF_UW   = OF_HSEC + SZ_SEC;
constexpr size_t OF_US   = OF_UW   + SZ_NODE;
constexpr size_t OF_USEC = OF_US   + SZ_NODE;
constexpr size_t OF_Z    = OF_USEC + SZ_NODE;      // zlin / gemm scratch
constexpr size_t OF_FFNH = OF_Z    + SZ_NODE;
constexpr size_t OF_ALWS = OF_FFNH + SZ_FFN;
constexpr size_t OF_ALWD = OF_ALWS + SZ_AL;
constexpr size_t OF_ALSS = OF_ALWD + SZ_AL;
constexpr size_t OF_ALSD = OF_ALSS + SZ_AL;
constexpr size_t OF_ALXS = OF_ALSD + SZ_AL;        // section src al  (512*8)
constexpr size_t OF_ALXD = OF_ALXS + SZ_ALSEC;
constexpr size_t POOL_FLOATS = OF_ALXD + SZ_AL;

__device__ float g_pool[POOL_FLOATS];

// int scratch: edge index (CSR sorted), rowptr, counts
constexpr size_t IOF_EIDX = 0;
constexpr size_t IOF_ROWP = IOF_EIDX + 65536;
constexpr size_t IOF_CNT  = IOF_ROWP + 4097;
constexpr size_t IPOOL_INTS = IOF_CNT + 4096;

__device__ int g_ipool[IPOOL_INTS];

// ---------------------------------------------------------------------------
// SGEMM: C[M,N] = A[M,K] @ B[K,N]   (+= if accum)
// 128x128 tile, BK=16, 256 threads, 8x8 microtile
// ---------------------------------------------------------------------------
#define BM 128
#define BN 128
#define BK 16

__global__ void sgemm_kernel(const float* __restrict__ A, const float* __restrict__ B,
                             float* __restrict__ C, int M, int N, int K, int accum)
{
    __shared__ float As[BK][BM];
    __shared__ float Bs[BK][BN];

    const int bm = blockIdx.y * BM;
    const int bn = blockIdx.x * BN;
    const int tid = threadIdx.x;
    const int tx = tid & 15;   // n direction
    const int ty = tid >> 4;   // m direction

    float acc[8][8];
#pragma unroll
    for (int i = 0; i < 8; i++)
#pragma unroll
        for (int j = 0; j < 8; j++) acc[i][j] = 0.f;

    for (int k0 = 0; k0 < K; k0 += BK) {
        // load A tile (128 x 16), transposed into As[k][m]
#pragma unroll
        for (int i = 0; i < 8; i++) {
            int lin = tid + i * 256;
            int m = lin >> 4, k = lin & 15;
            int gm = bm + m, gk = k0 + k;
            As[k][m] = (gm < M && gk < K) ? A[(size_t)gm * K + gk] : 0.f;
        }
        // load B tile (16 x 128)
#pragma unroll
        for (int i = 0; i < 8; i++) {
            int lin = tid + i * 256;
            int k = lin >> 7, n = lin & 127;
            int gk = k0 + k, gn = bn + n;
            Bs[k][n] = (gk < K && gn < N) ? B[(size_t)gk * N + gn] : 0.f;
        }
        __syncthreads();

#pragma unroll
        for (int k = 0; k < BK; k++) {
            float4 a0 = *(const float4*)&As[k][ty * 8];
            float4 a1 = *(const float4*)&As[k][ty * 8 + 4];
            float4 b0 = *(const float4*)&Bs[k][tx * 8];
            float4 b1 = *(const float4*)&Bs[k][tx * 8 + 4];
            float av[8] = {a0.x, a0.y, a0.z, a0.w, a1.x, a1.y, a1.z, a1.w};
            float bv[8] = {b0.x, b0.y, b0.z, b0.w, b1.x, b1.y, b1.z, b1.w};
#pragma unroll
            for (int i = 0; i < 8; i++)
#pragma unroll
                for (int j = 0; j < 8; j++) acc[i][j] += av[i] * bv[j];
        }
        __syncthreads();
    }

#pragma unroll
    for (int i = 0; i < 8; i++) {
        int gm = bm + ty * 8 + i;
        if (gm >= M) continue;
        float* Crow = C + (size_t)gm * N;
#pragma unroll
        for (int j = 0; j < 8; j++) {
            int gn = bn + tx * 8 + j;
            if (gn >= N) continue;
            if (accum) Crow[gn] += acc[i][j];
            else       Crow[gn]  = acc[i][j];
        }
    }
}

// ---------------------------------------------------------------------------
// Per-node attention logits: al[n,h] = sum_c h[n, h*CH+c] * a[h,c]
// one block per node, warp w handles head w
// ---------------------------------------------------------------------------
__global__ void node_alpha_kernel(const float* __restrict__ h, const float* __restrict__ a,
                                  float* __restrict__ al)
{
    int node = blockIdx.x;
    int w = threadIdx.x >> 5, lane = threadIdx.x & 31;
    const float4* hv = (const float4*)(h + (size_t)node * HC + w * CH);
    const float4* av = (const float4*)(a + w * CH);
    float s = 0.f;
#pragma unroll
    for (int i = 0; i < 5; i++) {
        float4 x = hv[lane + 32 * i];
        float4 y = av[lane + 32 * i];
        s += x.x * y.x + x.y * y.y + x.z * y.z + x.w * y.w;
    }
#pragma unroll
    for (int o = 16; o; o >>= 1) s += __shfl_xor_sync(0xffffffffu, s, o);
    if (lane == 0) al[node * H_HEADS + w] = s;
}

// ---------------------------------------------------------------------------
// CSR build
// ---------------------------------------------------------------------------
__global__ void count_kernel(const int* __restrict__ dst, int* __restrict__ cnt, int E)
{
    int e = blockIdx.x * blockDim.x + threadIdx.x;
    if (e < E) atomicAdd(&cnt[min(dst[e], NS - 1)], 1);
}

__global__ void scan_kernel(const int* __restrict__ cnt, int* __restrict__ rowptr)
{
    __shared__ int sdata[1024];
    int t = threadIdx.x;             // 1024 threads, 4 elems each -> 4096
    int base = t * 4;
    int a0 = cnt[base], a1 = cnt[base + 1], a2 = cnt[base + 2], a3 = cnt[base + 3];
    int s = a0 + a1 + a2 + a3;
    sdata[t] = s;
    __syncthreads();
    for (int off = 1; off < 1024; off <<= 1) {
        int v = (t >= off) ? sdata[t - off] : 0;
        __syncthreads();
        sdata[t] += v;
        __syncthreads();
    }
    int excl = sdata[t] - s;
    rowptr[base]     = excl;
    rowptr[base + 1] = excl + a0;
    rowptr[base + 2] = excl + a0 + a1;
    rowptr[base + 3] = excl + a0 + a1 + a2;
    if (t == 1023) rowptr[4096] = sdata[1023];
}

__global__ void scatter_kernel(const int* __restrict__ dst, const int* __restrict__ rowptr,
                               int* __restrict__ cursor, int* __restrict__ eidx, int E)
{
    int e = blockIdx.x * blockDim.x + threadIdx.x;
    if (e < E) {
        int d = min(dst[e], NS - 1);
        int pos = atomicAdd(&cursor[d], 1);
        eidx[rowptr[d] + pos] = e;
    }
}

// ---------------------------------------------------------------------------
// Fused GAT: per-dst edge softmax + weighted aggregation + bias + ELU
// one block (256 threads) per destination sentence
// ---------------------------------------------------------------------------
__device__ __forceinline__ float lrelu(float x) { return x > 0.f ? x : NEG_SLOPE * x; }
__device__ __forceinline__ float eluf(float x)  { return x > 0.f ? x : expf(x) - 1.f; }

#define CHUNK 128

__global__ void gat_kernel(const int* __restrict__ eidx, const int* __restrict__ rowptr,
                           const int* __restrict__ esrc,
                           const float* __restrict__ al_s, const float* __restrict__ al_d,
                           const float* __restrict__ hsrc, const float* __restrict__ bias,
                           float* __restrict__ U, int n_src_m1)
{
    const int d = blockIdx.x;
    const int tid = threadIdx.x;
    const int w = tid >> 5, lane = tid & 31;

    __shared__ float ald8[H_HEADS];
    __shared__ float alpha_s[CHUNK * H_HEADS];
    __shared__ int   s_idx[CHUNK];

    const int r0 = rowptr[d];
    const int deg = rowptr[d + 1] - r0;

    if (tid < H_HEADS) ald8[tid] = al_d[d * H_HEADS + tid];
    __syncthreads();

    // pass A: per-head streaming max and denominator (warp w = head w)
    float mx = -3.4e38f;
    for (int e = lane; e < deg; e += 32) {
        int s = min(esrc[eidx[r0 + e]], n_src_m1);
        float v = lrelu(al_s[s * H_HEADS + w] + ald8[w]);
        mx = fmaxf(mx, v);
    }
#pragma unroll
    for (int o = 16; o; o >>= 1) mx = fmaxf(mx, __shfl_xor_sync(0xffffffffu, mx, o));
    float dn = 0.f;
    for (int e = lane; e < deg; e += 32) {
        int s = min(esrc[eidx[r0 + e]], n_src_m1);
        float v = lrelu(al_s[s * H_HEADS + w] + ald8[w]);
        dn += expf(v - mx);
    }
#pragma unroll
    for (int o = 16; o; o >>= 1) dn += __shfl_xor_sync(0xffffffffu, dn, o);
    const float invden = 1.f / (dn + 1e-16f);

    // channel accumulators: thread owns float4 at float offset tid*4 + j*1024
    float4 acc[5];
#pragma unroll
    for (int j = 0; j < 5; j++) acc[j] = make_float4(0.f, 0.f, 0.f, 0.f);
    int hj[5];
#pragma unroll
    for (int j = 0; j < 5; j++) hj[j] = (tid * 4 + j * 1024) / CH;

    for (int cs = 0; cs < deg; cs += CHUNK) {
        int cnt = min(CHUNK, deg - cs);
        __syncthreads();
        for (int e = lane; e < cnt; e += 32) {
            int ei = eidx[r0 + cs + e];
            int s = min(esrc[ei], n_src_m1);
            float v = lrelu(al_s[s * H_HEADS + w] + ald8[w]);
            alpha_s[e * H_HEADS + w] = expf(v - mx) * invden;
            if (w == 0) s_idx[e] = s;
        }
        __syncthreads();
        for (int e = 0; e < cnt; e++) {
            int s = s_idx[e];
            const float4* hv = (const float4*)(hsrc + (size_t)s * HC);
#pragma unroll
            for (int j = 0; j < 5; j++) {
                float a = alpha_s[e * H_HEADS + hj[j]];
                float4 v = hv[tid + j * 256];
                acc[j].x += a * v.x; acc[j].y += a * v.y;
                acc[j].z += a * v.z; acc[j].w += a * v.w;
            }
        }
    }

    // epilogue: + bias, ELU
    float4* Urow = (float4*)(U + (size_t)d * HC);
    const float4* bv = (const float4*)bias;
#pragma unroll
    for (int j = 0; j < 5; j++) {
        float4 b = bv[tid + j * 256];
        float4 o;
        o.x = eluf(acc[j].x + b.x); o.y = eluf(acc[j].y + b.y);
        o.z = eluf(acc[j].z + b.z); o.w = eluf(acc[j].w + b.w);
        Urow[tid + j * 256] = o;
    }
}

// ---------------------------------------------------------------------------
// Elementwise epilogues
// ---------------------------------------------------------------------------
__global__ void fusion_kernel(const float* __restrict__ zlin, const float* __restrict__ bf,
                              const float* __restrict__ a, const float* __restrict__ b,
                              float* __restrict__ U, int total4)
{
    int i = blockIdx.x * blockDim.x + threadIdx.x;
    if (i >= total4) return;
    int col4 = i % (HC / 4);
    float4 zl = ((const float4*)zlin)[i];
    float4 bb = ((const float4*)bf)[col4];
    float4 av = ((const float4*)a)[i];
    float4 bvv = ((const float4*)b)[i];
    float4 o;
    float z;
    z = 1.f / (1.f + expf(-(zl.x + bb.x))); o.x = z * av.x + (1.f - z) * bvv.x;
    z = 1.f / (1.f + expf(-(zl.y + bb.y))); o.y = z * av.y + (1.f - z) * bvv.y;
    z = 1.f / (1.f + expf(-(zl.z + bb.z))); o.z = z * av.z + (1.f - z) * bvv.z;
    z = 1.f / (1.f + expf(-(zl.w + bb.w))); o.w = z * av.w + (1.f - z) * bvv.w;
    ((float4*)U)[i] = o;
}

__global__ void bias_relu_kernel(float* __restrict__ x, const float* __restrict__ b, int total4, int cols4)
{
    int i = blockIdx.x * blockDim.x + threadIdx.x;
    if (i >= total4) return;
    float4 v = ((float4*)x)[i];
    float4 bb = ((const float4*)b)[i % cols4];
    v.x = fmaxf(v.x + bb.x, 0.f); v.y = fmaxf(v.y + bb.y, 0.f);
    v.z = fmaxf(v.z + bb.z, 0.f); v.w = fmaxf(v.w + bb.w, 0.f);
    ((float4*)x)[i] = v;
}

__global__ void final_kernel(const float* __restrict__ g, const float* __restrict__ b2,
                             const float* __restrict__ Hs, float* __restrict__ out, int total4, int cols4)
{
    int i = blockIdx.x * blockDim.x + threadIdx.x;
    if (i >= total4) return;
    float4 gv = ((const float4*)g)[i];
    float4 bb = ((const float4*)b2)[i % cols4];
    float4 hv = ((const float4*)Hs)[i];
    float4 o;
    o.x = hv.x + gv.x + bb.x; o.y = hv.y + gv.y + bb.y;
    o.z = hv.z + gv.z + bb.z; o.w = hv.w + gv.w + bb.w;
    ((float4*)out)[i] = o;
}

// ---------------------------------------------------------------------------
// Host launcher
// ---------------------------------------------------------------------------
static inline void run_sgemm(const float* A, const float* B, float* C,
                             int M, int N, int K, int accum)
{
    dim3 grid((N + BN - 1) / BN, (M + BM - 1) / BM);
    sgemm_kernel<<<grid, 256>>>(A, B, C, M, N, K, accum);
}

static inline void run_gat(const int* edges, int E,
                           const float* al_s, const float* al_d,
                           const float* hsrc, const float* bias,
                           float* U, int n_src, int* ip)
{
    const int* src = edges;
    const int* dst = edges + E;
    int* eidx = ip + IOF_EIDX;
    int* rowp = ip + IOF_ROWP;
    int* cnt  = ip + IOF_CNT;
    cudaMemsetAsync(cnt, 0, 4096 * sizeof(int));
    count_kernel<<<(E + 255) / 256, 256>>>(dst, cnt, E);
    scan_kernel<<<1, 1024>>>(cnt, rowp);
    cudaMemsetAsync(cnt, 0, 4096 * sizeof(int));
    scatter_kernel<<<(E + 255) / 256, 256>>>(dst, rowp, cnt, eidx, E);
    gat_kernel<<<NS, 256>>>(eidx, rowp, src, al_s, al_d, hsrc, bias, U, n_src - 1);
}

extern "C" void kernel_launch(void* const* d_in, const int* in_sizes, int n_in,
                              void* d_out, int out_size)
{
    const float* Hs     = (const float*)d_in[0];
    const float* Hw     = (const float*)d_in[1];
    const float* HSc    = (const float*)d_in[2];
    const int*   w2s    = (const int*)d_in[3];
    const int*   s2s    = (const int*)d_in[4];
    const int*   S2s    = (const int*)d_in[5];
    const float* Ww_src = (const float*)d_in[6];
    const float* Ww_dst = (const float*)d_in[7];
    const float* aw_src = (const float*)d_in[8];
    const float* aw_dst = (const float*)d_in[9];
    const float* bw     = (const float*)d_in[10];
    const float* Ws     = (const float*)d_in[11];
    const float* as_src = (const float*)d_in[12];
    const float* as_dst = (const float*)d_in[13];
    const float* bs     = (const float*)d_in[14];
    const float* WS_src = (const float*)d_in[15];
    const float* WS_dst = (const float*)d_in[16];
    const float* aS_src = (const float*)d_in[17];
    const float* aS_dst = (const float*)d_in[18];
    const float* bS     = (const float*)d_in[19];
    const float* Wf1    = (const float*)d_in[20];
    const float* bf1    = (const float*)d_in[21];
    const float* Wf2    = (const float*)d_in[22];
    const float* bf2    = (const float*)d_in[23];
    const float* W1     = (const float*)d_in[24];
    const float* b1     = (const float*)d_in[25];
    const float* W2     = (const float*)d_in[26];
    const float* b2     = (const float*)d_in[27];
    float* out = (float*)d_out;

    const int E_w = in_sizes[3] / 2;   // 65536
    const int E_s = in_sizes[4] / 2;   // 32768
    const int E_S = in_sizes[5] / 2;   // 4096

    float* pool = nullptr;
    int*   ip   = nullptr;
    cudaGetSymbolAddress((void**)&pool, g_pool);
    cudaGetSymbolAddress((void**)&ip,   g_ipool);

    float* hsw  = pool + OF_HSW;
    float* hdw  = pool + OF_HDW;
    float* hss  = pool + OF_HSS;
    float* hdS  = pool + OF_HDS;
    float* hSec = pool + OF_HSEC;
    float* Uw   = pool + OF_UW;
    float* Us   = pool + OF_US;
    float* USc  = pool + OF_USEC;
    float* zbuf = pool + OF_Z;
    float* ffnh = pool + OF_FFNH;
    float* alws = pool + OF_ALWS;
    float* alwd = pool + OF_ALWD;
    float* alss = pool + OF_ALSS;
    float* alsd = pool + OF_ALSD;
    float* alxs = pool + OF_ALXS;
    float* alxd = pool + OF_ALXD;

    // ---- projections (src word indices are always < NS, so only 4096 word rows matter)
    run_sgemm(Hw,  Ww_src, hsw,  NS,   HC, 300, 0);
    run_sgemm(Hs,  Ww_dst, hdw,  NS,   HC, 640, 0);
    run_sgemm(Hs,  Ws,     hss,  NS,   HC, 640, 0);
    run_sgemm(HSc, WS_src, hSec, NSEC, HC, 512, 0);
    run_sgemm(Hs,  WS_dst, hdS,  NS,   HC, 640, 0);

    // ---- attention logits
    node_alpha_kernel<<<NS,   256>>>(hsw,  aw_src, alws);
    node_alpha_kernel<<<NS,   256>>>(hdw,  aw_dst, alwd);
    node_alpha_kernel<<<NS,   256>>>(hss,  as_src, alss);
    node_alpha_kernel<<<NS,   256>>>(hss,  as_dst, alsd);
    node_alpha_kernel<<<NSEC, 256>>>(hSec, aS_src, alxs);
    node_alpha_kernel<<<NS,   256>>>(hdS,  aS_dst, alxd);

    // ---- GATs (CSR + fused softmax/aggregate/bias/ELU)
    run_gat(w2s, E_w, alws, alwd, hsw,  bw, Uw,  NS,   ip);
    run_gat(s2s, E_s, alss, alsd, hss,  bs, Us,  NS,   ip);
    run_gat(S2s, E_S, alxs, alxd, hSec, bS, USc, NSEC, ip);

    // ---- fusion 1: U1 = z*Uw + (1-z)*Us, z = sigmoid([Uw;Us]@Wf1 + bf1)
    run_sgemm(Uw, Wf1,                    zbuf, NS, HC, HC, 0);
    run_sgemm(Us, Wf1 + (size_t)HC * HC,  zbuf, NS, HC, HC, 1);
    {
        int total4 = NS * HC / 4;
        fusion_kernel<<<(total4 + 255) / 256, 256>>>(zbuf, bf1, Uw, Us, Uw, total4); // U1 -> Uw
    }

    // ---- fusion 2: U2 = z*U1 + (1-z)*US
    run_sgemm(Uw,  Wf2,                   zbuf, NS, HC, HC, 0);
    run_sgemm(USc, Wf2 + (size_t)HC * HC, zbuf, NS, HC, HC, 1);
    {
        int total4 = NS * HC / 4;
        fusion_kernel<<<(total4 + 255) / 256, 256>>>(zbuf, bf2, Uw, USc, Uw, total4); // U2 -> Uw
    }

    // ---- FFN + residual
    run_sgemm(Uw, W1, ffnh, NS, 640, HC, 0);
    {
        int total4 = NS * 640 / 4;
        bias_relu_kernel<<<(total4 + 255) / 256, 256>>>(ffnh, b1, total4, 640 / 4);
    }
    run_sgemm(ffnh, W2, zbuf, NS, 640, 640, 0);
    {
        int total4 = NS * 640 / 4;
        final_kernel<<<(total4 + 255) / 256, 256>>>(zbuf, b2, Hs, out, total4, 640 / 4);
    }
}

// round 2
// speedup vs baseline: 1.0018x; 1.0018x over previous
#include <cuda_runtime.h>
#include <cstdint>

// ---------------------------------------------------------------------------
// Problem constants
// ---------------------------------------------------------------------------
#define H_HEADS 8
#define CH      640
#define HC      5120           // H_HEADS * CH
#define NS      4096
#define NSEC    512
#define NEG_SLOPE 0.2f

// ---------------------------------------------------------------------------
// Scratch pool (static device allocations only; no cudaMalloc anywhere)
// ---------------------------------------------------------------------------
constexpr size_t SZ_NODE  = (size_t)NS * HC;       // 20,971,520 floats
constexpr size_t SZ_SEC   = (size_t)NSEC * HC;     //  2,621,440
constexpr size_t SZ_FFN   = (size_t)NS * 640;      //  2,621,440
constexpr size_t SZ_AL    = (size_t)NS * H_HEADS;  //     32,768
constexpr size_t SZ_ALSEC = (size_t)NSEC * H_HEADS;//      4,096

constexpr size_t OF_HSW  = 0;                      // word-src projection (rows 0..4095)
constexpr size_t OF_HDW  = OF_HSW  + SZ_NODE;
constexpr size_t OF_HSS  = OF_HDW  + SZ_NODE;      // sentence projection (src+dst)
constexpr size_t OF_HDS  = OF_HSS  + SZ_NODE;      // section-gat dst projection
constexpr size_t OF_HSEC = OF_HDS  + SZ_NODE;      // section src projection
constexpr size_t OF_UW   = OF_HSEC + SZ_SEC;
constexpr size_t OF_US   = OF_UW   + SZ_NODE;
constexpr size_t OF_USEC = OF_US   + SZ_NODE;
constexpr size_t OF_Z    = OF_USEC + SZ_NODE;      // zlin / gemm scratch
constexpr size_t OF_FFNH = OF_Z    + SZ_NODE;
constexpr size_t OF_ALWS = OF_FFNH + SZ_FFN;
constexpr size_t OF_ALWD = OF_ALWS + SZ_AL;
constexpr size_t OF_ALSS = OF_ALWD + SZ_AL;
constexpr size_t OF_ALSD = OF_ALSS + SZ_AL;
constexpr size_t OF_ALXS = OF_ALSD + SZ_AL;        // section src al  (512*8)
constexpr size_t OF_ALXD = OF_ALXS + SZ_ALSEC;
constexpr size_t POOL_FLOATS = OF_ALXD + SZ_AL;

__device__ float g_pool[POOL_FLOATS];

// int scratch: edge index (CSR sorted), rowptr, counts
constexpr size_t IOF_EIDX = 0;
constexpr size_t IOF_ROWP = IOF_EIDX + 65536;
constexpr size_t IOF_CNT  = IOF_ROWP + 4097;
constexpr size_t IPOOL_INTS = IOF_CNT + 4096;

__device__ int g_ipool[IPOOL_INTS];

// ---------------------------------------------------------------------------
// SGEMM: C[M,N] = A[M,K] @ B[K,N]   (+= if accum)
// 128x128 tile, BK=16, 256 threads, 8x8 microtile
// ---------------------------------------------------------------------------
#define BM 128
#define BN 128
#define BK 16

__global__ void sgemm_kernel(const float* __restrict__ A, const float* __restrict__ B,
                             float* __restrict__ C, int M, int N, int K, int accum)
{
    __shared__ float As[BK][BM];
    __shared__ float Bs[BK][BN];

    const int bm = blockIdx.y * BM;
    const int bn = blockIdx.x * BN;
    const int tid = threadIdx.x;
    const int tx = tid & 15;   // n direction
    const int ty = tid >> 4;   // m direction

    float acc[8][8];
#pragma unroll
    for (int i = 0; i < 8; i++)
#pragma unroll
        for (int j = 0; j < 8; j++) acc[i][j] = 0.f;

    for (int k0 = 0; k0 < K; k0 += BK) {
        // load A tile (128 x 16), transposed into As[k][m]
#pragma unroll
        for (int i = 0; i < 8; i++) {
            int lin = tid + i * 256;
            int m = lin >> 4, k = lin & 15;
            int gm = bm + m, gk = k0 + k;
            As[k][m] = (gm < M && gk < K) ? A[(size_t)gm * K + gk] : 0.f;
        }
        // load B tile (16 x 128)
#pragma unroll
        for (int i = 0; i < 8; i++) {
            int lin = tid + i * 256;
            int k = lin >> 7, n = lin & 127;
            int gk = k0 + k, gn = bn + n;
            Bs[k][n] = (gk < K && gn < N) ? B[(size_t)gk * N + gn] : 0.f;
        }
        __syncthreads();

#pragma unroll
        for (int k = 0; k < BK; k++) {
            float4 a0 = *(const float4*)&As[k][ty * 8];
            float4 a1 = *(const float4*)&As[k][ty * 8 + 4];
            float4 b0 = *(const float4*)&Bs[k][tx * 8];
            float4 b1 = *(const float4*)&Bs[k][tx * 8 + 4];
            float av[8] = {a0.x, a0.y, a0.z, a0.w, a1.x, a1.y, a1.z, a1.w};
            float bv[8] = {b0.x, b0.y, b0.z, b0.w, b1.x, b1.y, b1.z, b1.w};
#pragma unroll
            for (int i = 0; i < 8; i++)
#pragma unroll
                for (int j = 0; j < 8; j++) acc[i][j] += av[i] * bv[j];
        }
        __syncthreads();
    }

#pragma unroll
    for (int i = 0; i < 8; i++) {
        int gm = bm + ty * 8 + i;
        if (gm >= M) continue;
        float* Crow = C + (size_t)gm * N;
#pragma unroll
        for (int j = 0; j < 8; j++) {
            int gn = bn + tx * 8 + j;
            if (gn >= N) continue;
            if (accum) Crow[gn] += acc[i][j];
            else       Crow[gn]  = acc[i][j];
        }
    }
}

// ---------------------------------------------------------------------------
// Per-node attention logits: al[n,h] = sum_c h[n, h*CH+c] * a[h,c]
// one block per node, warp w handles head w
// ---------------------------------------------------------------------------
__global__ void node_alpha_kernel(const float* __restrict__ h, const float* __restrict__ a,
                                  float* __restrict__ al)
{
    int node = blockIdx.x;
    int w = threadIdx.x >> 5, lane = threadIdx.x & 31;
    const float4* hv = (const float4*)(h + (size_t)node * HC + w * CH);
    const float4* av = (const float4*)(a + w * CH);
    float s = 0.f;
#pragma unroll
    for (int i = 0; i < 5; i++) {
        float4 x = hv[lane + 32 * i];
        float4 y = av[lane + 32 * i];
        s += x.x * y.x + x.y * y.y + x.z * y.z + x.w * y.w;
    }
#pragma unroll
    for (int o = 16; o; o >>= 1) s += __shfl_xor_sync(0xffffffffu, s, o);
    if (lane == 0) al[node * H_HEADS + w] = s;
}

// ---------------------------------------------------------------------------
// CSR build
// ---------------------------------------------------------------------------
__global__ void count_kernel(const int* __restrict__ dst, int* __restrict__ cnt, int E)
{
    int e = blockIdx.x * blockDim.x + threadIdx.x;
    if (e < E) atomicAdd(&cnt[min(dst[e], NS - 1)], 1);
}

__global__ void scan_kernel(const int* __restrict__ cnt, int* __restrict__ rowptr)
{
    __shared__ int sdata[1024];
    int t = threadIdx.x;             // 1024 threads, 4 elems each -> 4096
    int base = t * 4;
    int a0 = cnt[base], a1 = cnt[base + 1], a2 = cnt[base + 2], a3 = cnt[base + 3];
    int s = a0 + a1 + a2 + a3;
    sdata[t] = s;
    __syncthreads();
    for (int off = 1; off < 1024; off <<= 1) {
        int v = (t >= off) ? sdata[t - off] : 0;
        __syncthreads();
        sdata[t] += v;
        __syncthreads();
    }
    int excl = sdata[t] - s;
    rowptr[base]     = excl;
    rowptr[base + 1] = excl + a0;
    rowptr[base + 2] = excl + a0 + a1;
    rowptr[base + 3] = excl + a0 + a1 + a2;
    if (t == 1023) rowptr[4096] = sdata[1023];
}

__global__ void scatter_kernel(const int* __restrict__ dst, const int* __restrict__ rowptr,
                               int* __restrict__ cursor, int* __restrict__ eidx, int E)
{
    int e = blockIdx.x * blockDim.x + threadIdx.x;
    if (e < E) {
        int d = min(dst[e], NS - 1);
        int pos = atomicAdd(&cursor[d], 1);
        eidx[rowptr[d] + pos] = e;
    }
}

// ---------------------------------------------------------------------------
// Fused GAT: per-dst edge softmax + weighted aggregation + bias + ELU
// one block (256 threads) per destination sentence
// ---------------------------------------------------------------------------
__device__ __forceinline__ float lrelu(float x) { return x > 0.f ? x : NEG_SLOPE * x; }
__device__ __forceinline__ float eluf(float x)  { return x > 0.f ? x : expf(x) - 1.f; }

#define CHUNK 128

__global__ void gat_kernel(const int* __restrict__ eidx, const int* __restrict__ rowptr,
                           const int* __restrict__ esrc,
                           const float* __restrict__ al_s, const float* __restrict__ al_d,
                           const float* __restrict__ hsrc, const float* __restrict__ bias,
                           float* __restrict__ U, int n_src_m1)
{
    const int d = blockIdx.x;
    const int tid = threadIdx.x;
    const int w = tid >> 5, lane = tid & 31;

    __shared__ float ald8[H_HEADS];
    __shared__ float alpha_s[CHUNK * H_HEADS];
    __shared__ int   s_idx[CHUNK];

    const int r0 = rowptr[d];
    const int deg = rowptr[d + 1] - r0;

    if (tid < H_HEADS) ald8[tid] = al_d[d * H_HEADS + tid];
    __syncthreads();

    // pass A: per-head streaming max and denominator (warp w = head w)
    float mx = -3.4e38f;
    for (int e = lane; e < deg; e += 32) {
        int s = min(esrc[eidx[r0 + e]], n_src_m1);
        float v = lrelu(al_s[s * H_HEADS + w] + ald8[w]);
        mx = fmaxf(mx, v);
    }
#pragma unroll
    for (int o = 16; o; o >>= 1) mx = fmaxf(mx, __shfl_xor_sync(0xffffffffu, mx, o));
    float dn = 0.f;
    for (int e = lane; e < deg; e += 32) {
        int s = min(esrc[eidx[r0 + e]], n_src_m1);
        float v = lrelu(al_s[s * H_HEADS + w] + ald8[w]);
        dn += expf(v - mx);
    }
#pragma unroll
    for (int o = 16; o; o >>= 1) dn += __shfl_xor_sync(0xffffffffu, dn, o);
    const float invden = 1.f / (dn + 1e-16f);

    // channel accumulators: thread owns float4 at float offset tid*4 + j*1024
    float4 acc[5];
#pragma unroll
    for (int j = 0; j < 5; j++) acc[j] = make_float4(0.f, 0.f, 0.f, 0.f);
    int hj[5];
#pragma unroll
    for (int j = 0; j < 5; j++) hj[j] = (tid * 4 + j * 1024) / CH;

    for (int cs = 0; cs < deg; cs += CHUNK) {
        int cnt = min(CHUNK, deg - cs);
        __syncthreads();
        for (int e = lane; e < cnt; e += 32) {
            int ei = eidx[r0 + cs + e];
            int s = min(esrc[ei], n_src_m1);
            float v = lrelu(al_s[s * H_HEADS + w] + ald8[w]);
            alpha_s[e * H_HEADS + w] = expf(v - mx) * invden;
            if (w == 0) s_idx[e] = s;
        }
        __syncthreads();
        for (int e = 0; e < cnt; e++) {
            int s = s_idx[e];
            const float4* hv = (const float4*)(hsrc + (size_t)s * HC);
#pragma unroll
            for (int j = 0; j < 5; j++) {
                float a = alpha_s[e * H_HEADS + hj[j]];
                float4 v = hv[tid + j * 256];
                acc[j].x += a * v.x; acc[j].y += a * v.y;
                acc[j].z += a * v.z; acc[j].w += a * v.w;
            }
        }
    }

    // epilogue: + bias, ELU
    float4* Urow = (float4*)(U + (size_t)d * HC);
    const float4* bv = (const float4*)bias;
#pragma unroll
    for (int j = 0; j < 5; j++) {
        float4 b = bv[tid + j * 256];
        float4 o;
        o.x = eluf(acc[j].x + b.x); o.y = eluf(acc[j].y + b.y);
        o.z = eluf(acc[j].z + b.z); o.w = eluf(acc[j].w + b.w);
        Urow[tid + j * 256] = o;
    }
}

// ---------------------------------------------------------------------------
// Elementwise epilogues
// ---------------------------------------------------------------------------
__global__ void fusion_kernel(const float* __restrict__ zlin, const float* __restrict__ bf,
                              const float* __restrict__ a, const float* __restrict__ b,
                              float* __restrict__ U, int total4)
{
    int i = blockIdx.x * blockDim.x + threadIdx.x;
    if (i >= total4) return;
    int col4 = i % (HC / 4);
    float4 zl = ((const float4*)zlin)[i];
    float4 bb = ((const float4*)bf)[col4];
    float4 av = ((const float4*)a)[i];
    float4 bvv = ((const float4*)b)[i];
    float4 o;
    float z;
    z = 1.f / (1.f + expf(-(zl.x + bb.x))); o.x = z * av.x + (1.f - z) * bvv.x;
    z = 1.f / (1.f + expf(-(zl.y + bb.y))); o.y = z * av.y + (1.f - z) * bvv.y;
    z = 1.f / (1.f + expf(-(zl.z + bb.z))); o.z = z * av.z + (1.f - z) * bvv.z;
    z = 1.f / (1.f + expf(-(zl.w + bb.w))); o.w = z * av.w + (1.f - z) * bvv.w;
    ((float4*)U)[i] = o;
}

__global__ void bias_relu_kernel(float* __restrict__ x, const float* __restrict__ b, int total4, int cols4)
{
    int i = blockIdx.x * blockDim.x + threadIdx.x;
    if (i >= total4) return;
    float4 v = ((float4*)x)[i];
    float4 bb = ((const float4*)b)[i % cols4];
    v.x = fmaxf(v.x + bb.x, 0.f); v.y = fmaxf(v.y + bb.y, 0.f);
    v.z = fmaxf(v.z + bb.z, 0.f); v.w = fmaxf(v.w + bb.w, 0.f);
    ((float4*)x)[i] = v;
}

__global__ void final_kernel(const float* __restrict__ g, const float* __restrict__ b2,
                             const float* __restrict__ Hs, float* __restrict__ out, int total4, int cols4)
{
    int i = blockIdx.x * blockDim.x + threadIdx.x;
    if (i >= total4) return;
    float4 gv = ((const float4*)g)[i];
    float4 bb = ((const float4*)b2)[i % cols4];
    float4 hv = ((const float4*)Hs)[i];
    float4 o;
    o.x = hv.x + gv.x + bb.x; o.y = hv.y + gv.y + bb.y;
    o.z = hv.z + gv.z + bb.z; o.w = hv.w + gv.w + bb.w;
    ((float4*)out)[i] = o;
}

// ---------------------------------------------------------------------------
// Host launcher
// ---------------------------------------------------------------------------
static inline void run_sgemm(const float* A, const float* B, float* C,
                             int M, int N, int K, int accum)
{
    dim3 grid((N + BN - 1) / BN, (M + BM - 1) / BM);
    sgemm_kernel<<<grid, 256>>>(A, B, C, M, N, K, accum);
}

static inline void run_gat(const int* edges, int E,
                           const float* al_s, const float* al_d,
                           const float* hsrc, const float* bias,
                           float* U, int n_src, int* ip)
{
    const int* src = edges;
    const int* dst = edges + E;
    int* eidx = ip + IOF_EIDX;
    int* rowp = ip + IOF_ROWP;
    int* cnt  = ip + IOF_CNT;
    cudaMemsetAsync(cnt, 0, 4096 * sizeof(int));
    count_kernel<<<(E + 255) / 256, 256>>>(dst, cnt, E);
    scan_kernel<<<1, 1024>>>(cnt, rowp);
    cudaMemsetAsync(cnt, 0, 4096 * sizeof(int));
    scatter_kernel<<<(E + 255) / 256, 256>>>(dst, rowp, cnt, eidx, E);
    gat_kernel<<<NS, 256>>>(eidx, rowp, src, al_s, al_d, hsrc, bias, U, n_src - 1);
}

extern "C" void kernel_launch(void* const* d_in, const int* in_sizes, int n_in,
                              void* d_out, int out_size)
{
    const float* Hs     = (const float*)d_in[0];
    const float* Hw     = (const float*)d_in[1];
    const float* HSc    = (const float*)d_in[2];
    const int*   w2s    = (const int*)d_in[3];
    const int*   s2s    = (const int*)d_in[4];
    const int*   S2s    = (const int*)d_in[5];
    const float* Ww_src = (const float*)d_in[6];
    const float* Ww_dst = (const float*)d_in[7];
    const float* aw_src = (const float*)d_in[8];
    const float* aw_dst = (const float*)d_in[9];
    const float* bw     = (const float*)d_in[10];
    const float* Ws     = (const float*)d_in[11];
    const float* as_src = (const float*)d_in[12];
    const float* as_dst = (const float*)d_in[13];
    const float* bs     = (const float*)d_in[14];
    const float* WS_src = (const float*)d_in[15];
    const float* WS_dst = (const float*)d_in[16];
    const float* aS_src = (const float*)d_in[17];
    const float* aS_dst = (const float*)d_in[18];
    const float* bS     = (const float*)d_in[19];
    const float* Wf1    = (const float*)d_in[20];
    const float* bf1    = (const float*)d_in[21];
    const float* Wf2    = (const float*)d_in[22];
    const float* bf2    = (const float*)d_in[23];
    const float* W1     = (const float*)d_in[24];
    const float* b1     = (const float*)d_in[25];
    const float* W2     = (const float*)d_in[26];
    const float* b2     = (const float*)d_in[27];
    float* out = (float*)d_out;

    const int E_w = in_sizes[3] / 2;   // 65536
    const int E_s = in_sizes[4] / 2;   // 32768
    const int E_S = in_sizes[5] / 2;   // 4096

    float* pool = nullptr;
    int*   ip   = nullptr;
    cudaGetSymbolAddress((void**)&pool, g_pool);
    cudaGetSymbolAddress((void**)&ip,   g_ipool);

    float* hsw  = pool + OF_HSW;
    float* hdw  = pool + OF_HDW;
    float* hss  = pool + OF_HSS;
    float* hdS  = pool + OF_HDS;
    float* hSec = pool + OF_HSEC;
    float* Uw   = pool + OF_UW;
    float* Us   = pool + OF_US;
    float* USc  = pool + OF_USEC;
    float* zbuf = pool + OF_Z;
    float* ffnh = pool + OF_FFNH;
    float* alws = pool + OF_ALWS;
    float* alwd = pool + OF_ALWD;
    float* alss = pool + OF_ALSS;
    float* alsd = pool + OF_ALSD;
    float* alxs = pool + OF_ALXS;
    float* alxd = pool + OF_ALXD;

    // ---- projections (src word indices are always < NS, so only 4096 word rows matter)
    run_sgemm(Hw,  Ww_src, hsw,  NS,   HC, 300, 0);
    run_sgemm(Hs,  Ww_dst, hdw,  NS,   HC, 640, 0);
    run_sgemm(Hs,  Ws,     hss,  NS,   HC, 640, 0);
    run_sgemm(HSc, WS_src, hSec, NSEC, HC, 512, 0);
    run_sgemm(Hs,  WS_dst, hdS,  NS,   HC, 640, 0);

    // ---- attention logits
    node_alpha_kernel<<<NS,   256>>>(hsw,  aw_src, alws);
    node_alpha_kernel<<<NS,   256>>>(hdw,  aw_dst, alwd);
    node_alpha_kernel<<<NS,   256>>>(hss,  as_src, alss);
    node_alpha_kernel<<<NS,   256>>>(hss,  as_dst, alsd);
    node_alpha_kernel<<<NSEC, 256>>>(hSec, aS_src, alxs);
    node_alpha_kernel<<<NS,   256>>>(hdS,  aS_dst, alxd);

    // ---- GATs (CSR + fused softmax/aggregate/bias/ELU)
    run_gat(w2s, E_w, alws, alwd, hsw,  bw, Uw,  NS,   ip);
    run_gat(s2s, E_s, alss, alsd, hss,  bs, Us,  NS,   ip);
    run_gat(S2s, E_S, alxs, alxd, hSec, bS, USc, NSEC, ip);

    // ---- fusion 1: U1 = z*Uw + (1-z)*Us, z = sigmoid([Uw;Us]@Wf1 + bf1)
    run_sgemm(Uw, Wf1,                    zbuf, NS, HC, HC, 0);
    run_sgemm(Us, Wf1 + (size_t)HC * HC,  zbuf, NS, HC, HC, 1);
    {
        int total4 = NS * HC / 4;
        fusion_kernel<<<(total4 + 255) / 256, 256>>>(zbuf, bf1, Uw, Us, Uw, total4); // U1 -> Uw
    }

    // ---- fusion 2: U2 = z*U1 + (1-z)*US
    run_sgemm(Uw,  Wf2,                   zbuf, NS, HC, HC, 0);
    run_sgemm(USc, Wf2 + (size_t)HC * HC, zbuf, NS, HC, HC, 1);
    {
        int total4 = NS * HC / 4;
        fusion_kernel<<<(total4 + 255) / 256, 256>>>(zbuf, bf2, Uw, USc, Uw, total4); // U2 -> Uw
    }

    // ---- FFN + residual
    run_sgemm(Uw, W1, ffnh, NS, 640, HC, 0);
    {
        int total4 = NS * 640 / 4;
        bias_relu_kernel<<<(total4 + 255) / 256, 256>>>(ffnh, b1, total4, 640 / 4);
    }
    run_sgemm(ffnh, W2, zbuf, NS, 640, 640, 0);
    {
        int total4 = NS * 640 / 4;
        final_kernel<<<(total4 + 255) / 256, 256>>>(zbuf, b2, Hs, out, total4, 640 / 4);
    }
}

// round 4
// speedup vs baseline: 10.5676x; 10.5489x over previous
#include <cuda_runtime.h>
#include <cuda_fp16.h>
#include <cstdint>
#include <cstddef>

#define H_HEADS 8
#define CH      640
#define HC      5120
#define NS      4096
#define NSEC    512
#define NEG_SLOPE 0.2f

// ---------------------------------------------------------------------------
// Half scratch pool (static device memory only)
// ---------------------------------------------------------------------------
constexpr size_t TBL = (size_t)NS * HC;            // 20,971,520 halves

constexpr size_t H_HSW  = 0;
constexpr size_t H_HDW  = H_HSW  + TBL;
constexpr size_t H_HSS  = H_HDW  + TBL;
constexpr size_t H_HDS  = H_HSS  + TBL;
constexpr size_t H_HSEC = H_HDS  + TBL;                 // 512*5120
constexpr size_t H_UW   = H_HSEC + (size_t)NSEC * HC;
constexpr size_t H_US   = H_UW   + TBL;
constexpr size_t H_USC  = H_US   + TBL;
constexpr size_t H_U1   = H_USC  + TBL;
constexpr size_t H_U2   = H_U1   + TBL;
constexpr size_t H_FFNH = H_U2   + TBL;                 // 4096*640
constexpr size_t H_AHW  = H_FFNH + (size_t)NS * 640;    // 4096*320
constexpr size_t H_AHS  = H_AHW  + (size_t)NS * 320;    // 4096*640
constexpr size_t H_AHSC = H_AHS  + (size_t)NS * 640;    // 512*512
constexpr size_t H_WWS  = H_AHSC + (size_t)NSEC * 512;  // 5120*320
constexpr size_t H_WWD  = H_WWS  + (size_t)HC * 320;    // 5120*640
constexpr size_t H_WS   = H_WWD  + (size_t)HC * 640;
constexpr size_t H_WSS  = H_WS   + (size_t)HC * 640;    // 5120*512
constexpr size_t H_WSD  = H_WSS  + (size_t)HC * 512;
constexpr size_t H_F1A  = H_WSD  + (size_t)HC * 640;    // 5120*5120
constexpr size_t H_F1B  = H_F1A  + (size_t)HC * HC;
constexpr size_t H_F2A  = H_F1B  + (size_t)HC * HC;
constexpr size_t H_F2B  = H_F2A  + (size_t)HC * HC;
constexpr size_t H_W1   = H_F2B  + (size_t)HC * HC;     // 640*5120
constexpr size_t H_W2   = H_W1   + (size_t)640 * HC;    // 640*640
constexpr size_t HPOOL  = H_W2   + (size_t)640 * 640;

__device__ __half g_hpool[HPOOL];
__device__ float  g_fpool[6 * 32768];                   // attention logits

constexpr size_t IOF_EIDX = 0;
constexpr size_t IOF_ROWP = IOF_EIDX + 65536;
constexpr size_t IOF_CNT  = IOF_ROWP + 4097;
__device__ int g_ipool[IOF_CNT + 4096];

// ---------------------------------------------------------------------------
// PTX helpers (legacy tensor-core path: works on plain sm_103 target)
// ---------------------------------------------------------------------------
__device__ __forceinline__ uint32_t smem_u32(const void* p) {
    uint32_t a;
    asm("{ .reg .u64 t; cvta.to.shared.u64 t, %1; cvt.u32.u64 %0, t; }" : "=r"(a) : "l"(p));
    return a;
}
__device__ __forceinline__ void cp16(uint32_t dst, const void* src) {
    asm volatile("cp.async.cg.shared.global [%0], [%1], 16;" :: "r"(dst), "l"(src));
}
__device__ __forceinline__ void ldsm4(uint32_t* r, uint32_t addr) {
    asm volatile("ldmatrix.sync.aligned.m8n8.x4.shared.b16 {%0,%1,%2,%3}, [%4];"
                 : "=r"(r[0]), "=r"(r[1]), "=r"(r[2]), "=r"(r[3]) : "r"(addr));
}
__device__ __forceinline__ void mma16816(float* c, const uint32_t* a, uint32_t b0, uint32_t b1) {
    asm volatile("mma.sync.aligned.m16n8k16.row.col.f32.f16.f16.f32 "
                 "{%0,%1,%2,%3}, {%4,%5,%6,%7}, {%8,%9}, {%0,%1,%2,%3};"
                 : "+f"(c[0]), "+f"(c[1]), "+f"(c[2]), "+f"(c[3])
                 : "r"(a[0]), "r"(a[1]), "r"(a[2]), "r"(a[3]), "r"(b0), "r"(b1));
}

// ---------------------------------------------------------------------------
// fp16 GEMM: C[M,N] = A0[M,Kp0] @ B0[N,Kp0]^T (+ A1[M,Kp1] @ B1[N,Kp1]^T)
// tile 128x128, BK=64 halves (128B rows), 8 warps (2x4), 3-stage cp.async
// M, N multiples of 128; Kp multiples of 64. No bounds checks needed.
// ---------------------------------------------------------------------------
#define STG 32768
#define GT_SMEM (3 * STG)

#define MODE_STORE  0
#define MODE_FUSION 1
#define MODE_RELU   2
#define MODE_FINAL  3

__global__ void __launch_bounds__(256, 2)
hgemm_kernel(const __half* __restrict__ A0, const __half* __restrict__ B0, int Kp0,
             const __half* __restrict__ A1, const __half* __restrict__ B1, int Kp1,
             void* __restrict__ Cv, int N, int mode,
             const float* __restrict__ bias,
             const void* __restrict__ aux0, const void* __restrict__ aux1)
{
    extern __shared__ char smem[];
    const uint32_t sb = smem_u32(smem);
    const int tid  = threadIdx.x;
    const int lane = tid & 31;
    const int warp = tid >> 5;
    const int wm = warp & 1, wn = warp >> 1;
    const int m0 = blockIdx.x * 128;
    const int n0 = blockIdx.y * 128;

    const int KB0 = Kp0 >> 6;
    const int KB1 = B1 ? (Kp1 >> 6) : 0;
    const int KB  = KB0 + KB1;

    auto load_tile = [&](int kb, int slot) {
        const __half* A; const __half* B; int Kp, kof;
        if (kb < KB0) { A = A0; B = B0; Kp = Kp0; kof = kb << 6; }
        else          { A = A1; B = B1; Kp = Kp1; kof = (kb - KB0) << 6; }
        const uint32_t sa  = sb + slot * STG;
        const uint32_t sbb = sa + 16384;
#pragma unroll
        for (int i = 0; i < 4; i++) {
            int idx = tid + i * 256;
            int row = idx >> 3, g = idx & 7;
            cp16(sa + row * 128 + ((g ^ (row & 7)) << 4),
                 A + (size_t)(m0 + row) * Kp + kof + g * 8);
        }
#pragma unroll
        for (int i = 0; i < 4; i++) {
            int idx = tid + i * 256;
            int row = idx >> 3, g = idx & 7;
            cp16(sbb + row * 128 + ((g ^ (row & 7)) << 4),
                 B + (size_t)(n0 + row) * Kp + kof + g * 8);
        }
        asm volatile("cp.async.commit_group;" ::: "memory");
    };

    float acc[4][4][4];
#pragma unroll
    for (int i = 0; i < 4; i++)
#pragma unroll
        for (int j = 0; j < 4; j++)
#pragma unroll
            for (int q = 0; q < 4; q++) acc[i][j][q] = 0.f;

    load_tile(0, 0);
    load_tile(1, 1);

    const int arow = lane & 15, apart = lane >> 4;
    for (int kb = 0; kb < KB; kb++) {
        if (kb + 1 < KB) asm volatile("cp.async.wait_group 1;" ::: "memory");
        else             asm volatile("cp.async.wait_group 0;" ::: "memory");
        __syncthreads();
        if (kb + 2 < KB) load_tile(kb + 2, (kb + 2) % 3);

        const uint32_t sa  = sb + (kb % 3) * STG;
        const uint32_t sbb = sa + 16384;
#pragma unroll
        for (int ks = 0; ks < 4; ks++) {
            uint32_t a[4][4], b[2][4];
#pragma unroll
            for (int mf = 0; mf < 4; mf++) {
                int row = wm * 64 + mf * 16 + arow;
                ldsm4(a[mf], sa + row * 128 + ((((ks << 1) | apart) ^ (row & 7)) << 4));
            }
#pragma unroll
            for (int nfp = 0; nfp < 2; nfp++) {
                int row = wn * 32 + nfp * 16 + arow;
                ldsm4(b[nfp], sbb + row * 128 + ((((ks << 1) | apart) ^ (row & 7)) << 4));
            }
#pragma unroll
            for (int mf = 0; mf < 4; mf++)
#pragma unroll
                for (int nf = 0; nf < 4; nf++)
                    mma16816(acc[mf][nf], a[mf], b[nf >> 1][nf & 1], b[nf >> 1][(nf & 1) + 2]);
        }
    }

    // Fused epilogue
    const __half* x0 = (const __half*)aux0;
    const __half* x1 = (const __half*)aux1;
    const float*  rf = (const float*)aux0;
#pragma unroll
    for (int mf = 0; mf < 4; mf++)
#pragma unroll
        for (int nf = 0; nf < 4; nf++)
#pragma unroll
            for (int h = 0; h < 2; h++) {
                int row = m0 + wm * 64 + mf * 16 + (lane >> 2) + h * 8;
                int col = n0 + wn * 32 + nf * 8 + ((lane & 3) << 1);
                float v0 = acc[mf][nf][h * 2], v1 = acc[mf][nf][h * 2 + 1];
                size_t off = (size_t)row * N + col;
                if (mode == MODE_STORE) {
                    *(__half2*)((__half*)Cv + off) = __floats2half2_rn(v0, v1);
                } else if (mode == MODE_FUSION) {
                    float b0v = bias[col], b1v = bias[col + 1];
                    float2 av = __half22float2(*(const __half2*)(x0 + off));
                    float2 bv = __half22float2(*(const __half2*)(x1 + off));
                    float z0 = 1.f / (1.f + expf(-(v0 + b0v)));
                    float z1 = 1.f / (1.f + expf(-(v1 + b1v)));
                    *(__half2*)((__half*)Cv + off) =
                        __floats2half2_rn(z0 * av.x + (1.f - z0) * bv.x,
                                          z1 * av.y + (1.f - z1) * bv.y);
                } else if (mode == MODE_RELU) {
                    *(__half2*)((__half*)Cv + off) =
                        __floats2half2_rn(fmaxf(v0 + bias[col], 0.f),
                                          fmaxf(v1 + bias[col + 1], 0.f));
                } else {
                    *(float2*)((float*)Cv + off) =
                        make_float2(v0 + bias[col] + rf[off],
                                    v1 + bias[col + 1] + rf[off + 1]);
                }
            }
}

// ---------------------------------------------------------------------------
// fp32 -> fp16 convert with K padding
// ---------------------------------------------------------------------------
__global__ void convert_pad_kernel(const float* __restrict__ in, __half* __restrict__ out,
                                   int K, int Kp, int total)
{
    int i = blockIdx.x * blockDim.x + threadIdx.x;
    if (i >= total) return;
    int r = i / Kp, c = i % Kp;
    out[i] = __float2half(c < K ? in[(size_t)r * K + c] : 0.f);
}

// ---------------------------------------------------------------------------
// Transpose [R,C] fp32 -> [C,Rp] fp16 (zero pad R->Rp)
// ---------------------------------------------------------------------------
__global__ void tconv_kernel(const float* __restrict__ in, __half* __restrict__ out,
                             int R, int C, int Rp)
{
    __shared__ float t[32][33];
    int r0 = blockIdx.x * 32;   // input row / output col
    int c0 = blockIdx.y * 32;   // input col / output row
    int x = threadIdx.x, y = threadIdx.y;
#pragma unroll
    for (int j = 0; j < 32; j += 8) {
        int r = r0 + y + j, c = c0 + x;
        t[y + j][x] = (r < R && c < C) ? in[(size_t)r * C + c] : 0.f;
    }
    __syncthreads();
#pragma unroll
    for (int j = 0; j < 32; j += 8) {
        int orow = c0 + y + j, ocol = r0 + x;
        if (orow < C && ocol < Rp) out[(size_t)orow * Rp + ocol] = __float2half(t[x][y + j]);
    }
}

// ---------------------------------------------------------------------------
// Attention logits from half tables
// ---------------------------------------------------------------------------
__global__ void node_alpha_kernel(const __half* __restrict__ h, const float* __restrict__ a,
                                  float* __restrict__ al)
{
    int node = blockIdx.x;
    int w = threadIdx.x >> 5, lane = threadIdx.x & 31;
    const uint2* hv = (const uint2*)(h + (size_t)node * HC + w * CH);
    const float4* av = (const float4*)(a + w * CH);
    float s = 0.f;
#pragma unroll
    for (int i = 0; i < 5; i++) {
        uint2 raw = hv[lane + 32 * i];
        float4 y = av[lane + 32 * i];
        float2 f01 = __half22float2(*(__half2*)&raw.x);
        float2 f23 = __half22float2(*(__half2*)&raw.y);
        s += f01.x * y.x + f01.y * y.y + f23.x * y.z + f23.y * y.w;
    }
#pragma unroll
    for (int o = 16; o; o >>= 1) s += __shfl_xor_sync(0xffffffffu, s, o);
    if (lane == 0) al[node * H_HEADS + w] = s;
}

// ---------------------------------------------------------------------------
// CSR build
// ---------------------------------------------------------------------------
__global__ void count_kernel(const int* __restrict__ dst, int* __restrict__ cnt, int E)
{
    int e = blockIdx.x * blockDim.x + threadIdx.x;
    if (e < E) atomicAdd(&cnt[min(dst[e], NS - 1)], 1);
}

__global__ void scan_kernel(const int* __restrict__ cnt, int* __restrict__ rowptr)
{
    __shared__ int sd[1024];
    int t = threadIdx.x, base = t * 4;
    int a0 = cnt[base], a1 = cnt[base+1], a2 = cnt[base+2], a3 = cnt[base+3];
    int s = a0 + a1 + a2 + a3;
    sd[t] = s;
    __syncthreads();
    for (int off = 1; off < 1024; off <<= 1) {
        int v = (t >= off) ? sd[t - off] : 0;
        __syncthreads();
        sd[t] += v;
        __syncthreads();
    }
    int ex = sd[t] - s;
    rowptr[base] = ex; rowptr[base+1] = ex+a0; rowptr[base+2] = ex+a0+a1; rowptr[base+3] = ex+a0+a1+a2;
    if (t == 1023) rowptr[4096] = sd[1023];
}

__global__ void scatter_kernel(const int* __restrict__ dst, const int* __restrict__ rowptr,
                               int* __restrict__ cur, int* __restrict__ eidx, int E)
{
    int e = blockIdx.x * blockDim.x + threadIdx.x;
    if (e < E) {
        int d = min(dst[e], NS - 1);
        eidx[rowptr[d] + atomicAdd(&cur[d], 1)] = e;
    }
}

// ---------------------------------------------------------------------------
// Fused GAT: softmax + aggregate + bias + ELU  (half tables in, half U out)
// ---------------------------------------------------------------------------
__device__ __forceinline__ float lrelu(float x) { return x > 0.f ? x : NEG_SLOPE * x; }
__device__ __forceinline__ float eluf(float x)  { return x > 0.f ? x : expf(x) - 1.f; }
#define CHUNK 128

__global__ void gat_kernel(const int* __restrict__ eidx, const int* __restrict__ rowptr,
                           const int* __restrict__ esrc,
                           const float* __restrict__ al_s, const float* __restrict__ al_d,
                           const __half* __restrict__ hsrc, const float* __restrict__ bias,
                           __half* __restrict__ U, int n_src_m1)
{
    const int d = blockIdx.x;
    const int tid = threadIdx.x;
    const int w = tid >> 5, lane = tid & 31;

    __shared__ float ald8[H_HEADS];
    __shared__ float alpha_s[CHUNK * H_HEADS];
    __shared__ int   s_idx[CHUNK];

    const int r0 = rowptr[d];
    const int deg = rowptr[d + 1] - r0;

    if (tid < H_HEADS) ald8[tid] = al_d[d * H_HEADS + tid];
    __syncthreads();

    float mx = -3.4e38f;
    for (int e = lane; e < deg; e += 32) {
        int s = min(esrc[eidx[r0 + e]], n_src_m1);
        mx = fmaxf(mx, lrelu(al_s[s * H_HEADS + w] + ald8[w]));
    }
#pragma unroll
    for (int o = 16; o; o >>= 1) mx = fmaxf(mx, __shfl_xor_sync(0xffffffffu, mx, o));
    float dn = 0.f;
    for (int e = lane; e < deg; e += 32) {
        int s = min(esrc[eidx[r0 + e]], n_src_m1);
        dn += expf(lrelu(al_s[s * H_HEADS + w] + ald8[w]) - mx);
    }
#pragma unroll
    for (int o = 16; o; o >>= 1) dn += __shfl_xor_sync(0xffffffffu, dn, o);
    const float invden = 1.f / (dn + 1e-16f);

    float4 acc[5];
#pragma unroll
    for (int j = 0; j < 5; j++) acc[j] = make_float4(0.f, 0.f, 0.f, 0.f);
    int hj[5];
#pragma unroll
    for (int j = 0; j < 5; j++) hj[j] = (tid * 4 + j * 1024) / CH;

    for (int cs = 0; cs < deg; cs += CHUNK) {
        int cnt = min(CHUNK, deg - cs);
        __syncthreads();
        for (int e = lane; e < cnt; e += 32) {
            int s = min(esrc[eidx[r0 + cs + e]], n_src_m1);
            alpha_s[e * H_HEADS + w] = expf(lrelu(al_s[s * H_HEADS + w] + ald8[w]) - mx) * invden;
            if (w == 0) s_idx[e] = s;
        }
        __syncthreads();
        for (int e = 0; e < cnt; e++) {
            int s = s_idx[e];
            const uint2* hv = (const uint2*)(hsrc + (size_t)s * HC);
#pragma unroll
            for (int j = 0; j < 5; j++) {
                float a = alpha_s[e * H_HEADS + hj[j]];
                uint2 raw = hv[tid + j * 256];
                float2 f01 = __half22float2(*(__half2*)&raw.x);
                float2 f23 = __half22float2(*(__half2*)&raw.y);
                acc[j].x += a * f01.x; acc[j].y += a * f01.y;
                acc[j].z += a * f23.x; acc[j].w += a * f23.y;
            }
        }
    }

    __half2* Urow = (__half2*)(U + (size_t)d * HC);
    const float4* bv = (const float4*)bias;
#pragma unroll
    for (int j = 0; j < 5; j++) {
        float4 b = bv[tid + j * 256];
        int p = (tid + j * 256) * 2;
        Urow[p]     = __floats2half2_rn(eluf(acc[j].x + b.x), eluf(acc[j].y + b.y));
        Urow[p + 1] = __floats2half2_rn(eluf(acc[j].z + b.z), eluf(acc[j].w + b.w));
    }
}

// ---------------------------------------------------------------------------
// Host side
// ---------------------------------------------------------------------------
static void run_hgemm(const __half* A0, const __half* B0, int Kp0,
                      const __half* A1, const __half* B1, int Kp1,
                      void* C, int M, int N, int mode,
                      const float* bias, const void* aux0, const void* aux1)
{
    cudaFuncSetAttribute(hgemm_kernel, cudaFuncAttributeMaxDynamicSharedMemorySize, GT_SMEM);
    dim3 grid(M / 128, N / 128);
    hgemm_kernel<<<grid, 256, GT_SMEM>>>(A0, B0, Kp0, A1, B1, Kp1, C, N, mode, bias, aux0, aux1);
}

static void run_tconv(const float* in, __half* out, int R, int C, int Rp)
{
    dim3 b(32, 8), g((Rp + 31) / 32, (C + 31) / 32);
    tconv_kernel<<<g, b>>>(in, out, R, C, Rp);
}

static void run_cpad(const float* in, __half* out, int rows, int K, int Kp)
{
    int total = rows * Kp;
    convert_pad_kernel<<<(total + 255) / 256, 256>>>(in, out, K, Kp, total);
}

static void run_gat(const int* edges, int E,
                    const float* al_s, const float* al_d,
                    const __half* hsrc, const float* bias,
                    __half* U, int n_src, int* ip)
{
    const int* src = edges;
    const int* dst = edges + E;
    int* eidx = ip + IOF_EIDX;
    int* rowp = ip + IOF_ROWP;
    int* cnt  = ip + IOF_CNT;
    cudaMemsetAsync(cnt, 0, 4096 * sizeof(int));
    count_kernel<<<(E + 255) / 256, 256>>>(dst, cnt, E);
    scan_kernel<<<1, 1024>>>(cnt, rowp);
    cudaMemsetAsync(cnt, 0, 4096 * sizeof(int));
    scatter_kernel<<<(E + 255) / 256, 256>>>(dst, rowp, cnt, eidx, E);
    gat_kernel<<<NS, 256>>>(eidx, rowp, src, al_s, al_d, hsrc, bias, U, n_src - 1);
}

extern "C" void kernel_launch(void* const* d_in, const int* in_sizes, int n_in,
                              void* d_out, int out_size)
{
    const float* Hs     = (const float*)d_in[0];
    const float* Hw     = (const float*)d_in[1];
    const float* HSc    = (const float*)d_in[2];
    const int*   w2s    = (const int*)d_in[3];
    const int*   s2s    = (const int*)d_in[4];
    const int*   S2s    = (const int*)d_in[5];
    const float* Ww_src = (const float*)d_in[6];
    const float* Ww_dst = (const float*)d_in[7];
    const float* aw_src = (const float*)d_in[8];
    const float* aw_dst = (const float*)d_in[9];
    const float* bw     = (const float*)d_in[10];
    const float* Ws     = (const float*)d_in[11];
    const float* as_src = (const float*)d_in[12];
    const float* as_dst = (const float*)d_in[13];
    const float* bs     = (const float*)d_in[14];
    const float* WS_src = (const float*)d_in[15];
    const float* WS_dst = (const float*)d_in[16];
    const float* aS_src = (const float*)d_in[17];
    const float* aS_dst = (const float*)d_in[18];
    const float* bS     = (const float*)d_in[19];
    const float* Wf1    = (const float*)d_in[20];
    const float* bf1    = (const float*)d_in[21];
    const float* Wf2    = (const float*)d_in[22];
    const float* bf2    = (const float*)d_in[23];
    const float* W1     = (const float*)d_in[24];
    const float* b1     = (const float*)d_in[25];
    const float* W2     = (const float*)d_in[26];
    const float* b2     = (const float*)d_in[27];
    float* out = (float*)d_out;

    const int E_w = in_sizes[3] / 2;
    const int E_s = in_sizes[4] / 2;
    const int E_S = in_sizes[5] / 2;

    __half* hp = nullptr; float* fp = nullptr; int* ip = nullptr;
    cudaGetSymbolAddress((void**)&hp, g_hpool);
    cudaGetSymbolAddress((void**)&fp, g_fpool);
    cudaGetSymbolAddress((void**)&ip, g_ipool);

    __half* hsw  = hp + H_HSW;
    __half* hdw  = hp + H_HDW;
    __half* hss  = hp + H_HSS;
    __half* hdS  = hp + H_HDS;
    __half* hSec = hp + H_HSEC;
    __half* Uw   = hp + H_UW;
    __half* Us   = hp + H_US;
    __half* USc  = hp + H_USC;
    __half* U1   = hp + H_U1;
    __half* U2   = hp + H_U2;
    __half* ffnh = hp + H_FFNH;
    __half* ahw  = hp + H_AHW;
    __half* ahs  = hp + H_AHS;
    __half* ahsc = hp + H_AHSC;
    __half* wws  = hp + H_WWS;
    __half* wwd  = hp + H_WWD;
    __half* wsp  = hp + H_WS;
    __half* wss  = hp + H_WSS;
    __half* wsd  = hp + H_WSD;
    __half* f1a  = hp + H_F1A;
    __half* f1b  = hp + H_F1B;
    __half* f2a  = hp + H_F2A;
    __half* f2b  = hp + H_F2B;
    __half* w1t  = hp + H_W1;
    __half* w2t  = hp + H_W2;

    float* alws = fp;
    float* alwd = alws + 32768;
    float* alss = alwd + 32768;
    float* alsd = alss + 32768;
    float* alxs = alsd + 32768;
    float* alxd = alxs + 32768;

    // ---- convert activations to fp16 (K padded to mult of 64)
    run_cpad(Hw,  ahw,  NS,   300, 320);   // only first 4096 word rows are ever sources
    run_cpad(Hs,  ahs,  NS,   640, 640);
    run_cpad(HSc, ahsc, NSEC, 512, 512);

    // ---- transpose+convert weights to [N,Kp] fp16
    run_tconv(Ww_src, wws, 300, HC, 320);
    run_tconv(Ww_dst, wwd, 640, HC, 640);
    run_tconv(Ws,     wsp, 640, HC, 640);
    run_tconv(WS_src, wss, 512, HC, 512);
    run_tconv(WS_dst, wsd, 640, HC, 640);
    run_tconv(Wf1,                   f1a, HC, HC, HC);
    run_tconv(Wf1 + (size_t)HC * HC, f1b, HC, HC, HC);
    run_tconv(Wf2,                   f2a, HC, HC, HC);
    run_tconv(Wf2 + (size_t)HC * HC, f2b, HC, HC, HC);
    run_tconv(W1, w1t, HC, 640, HC);
    run_tconv(W2, w2t, 640, 640, 640);

    // ---- projections
    run_hgemm(ahw,  wws, 320, 0, 0, 0, hsw,  NS,   HC, MODE_STORE, 0, 0, 0);
    run_hgemm(ahs,  wwd, 640, 0, 0, 0, hdw,  NS,   HC, MODE_STORE, 0, 0, 0);
    run_hgemm(ahs,  wsp, 640, 0, 0, 0, hss,  NS,   HC, MODE_STORE, 0, 0, 0);
    run_hgemm(ahsc, wss, 512, 0, 0, 0, hSec, NSEC, HC, MODE_STORE, 0, 0, 0);
    run_hgemm(ahs,  wsd, 640, 0, 0, 0, hdS,  NS,   HC, MODE_STORE, 0, 0, 0);

    // ---- attention logits
    node_alpha_kernel<<<NS,   256>>>(hsw,  aw_src, alws);
    node_alpha_kernel<<<NS,   256>>>(hdw,  aw_dst, alwd);
    node_alpha_kernel<<<NS,   256>>>(hss,  as_src, alss);
    node_alpha_kernel<<<NS,   256>>>(hss,  as_dst, alsd);
    node_alpha_kernel<<<NSEC, 256>>>(hSec, aS_src, alxs);
    node_alpha_kernel<<<NS,   256>>>(hdS,  aS_dst, alxd);

    // ---- GATs
    run_gat(w2s, E_w, alws, alwd, hsw,  bw, Uw,  NS,   ip);
    run_gat(s2s, E_s, alss, alsd, hss,  bs, Us,  NS,   ip);
    run_gat(S2s, E_S, alxs, alxd, hSec, bS, USc, NSEC, ip);

    // ---- fusion gates (concat as two accumulated segments)
    run_hgemm(Uw, f1a, HC, Us,  f1b, HC, U1, NS, HC, MODE_FUSION, bf1, Uw, Us);
    run_hgemm(U1, f2a, HC, USc, f2b, HC, U2, NS, HC, MODE_FUSION, bf2, U1, USc);

    // ---- FFN + residual
    run_hgemm(U2,   w1t, HC,  0, 0, 0, ffnh, NS, 640, MODE_RELU,  b1, 0,  0);
    run_hgemm(ffnh, w2t, 640, 0, 0, 0, out,  NS, 640, MODE_FINAL, b2, Hs, 0);
}

// round 5
// speedup vs baseline: 10.8785x; 1.0294x over previous
#include <cuda_runtime.h>
#include <cuda_fp16.h>
#include <cstdint>
#include <cstddef>

#define H_HEADS 8
#define CH      640
#define HC      5120
#define NS      4096
#define NSEC    512
#define NEG_SLOPE 0.2f

// ---------------------------------------------------------------------------
// Half scratch pool
// ---------------------------------------------------------------------------
constexpr size_t TBL = (size_t)NS * HC;

constexpr size_t H_HSW  = 0;
constexpr size_t H_HSS  = H_HSW  + TBL;
constexpr size_t H_HSEC = H_HSS  + TBL;
constexpr size_t H_UW   = H_HSEC + (size_t)NSEC * HC;
constexpr size_t H_US   = H_UW   + TBL;
constexpr size_t H_USC  = H_US   + TBL;
constexpr size_t H_U1   = H_USC  + TBL;
constexpr size_t H_U2   = H_U1   + TBL;
constexpr size_t H_FFNH = H_U2   + TBL;
constexpr size_t H_AHW  = H_FFNH + (size_t)NS * 640;     // [4096,320]
constexpr size_t H_AHS  = H_AHW  + (size_t)NS * 320;     // [4096,640]
constexpr size_t H_AHSC = H_AHS  + (size_t)NS * 640;     // [512,512]
constexpr size_t H_WWS  = H_AHSC + (size_t)NSEC * 512;   // [320,5120]
constexpr size_t H_WS   = H_WWS  + (size_t)320 * HC;     // [640,5120]
constexpr size_t H_WSS  = H_WS   + (size_t)640 * HC;     // [512,5120]
constexpr size_t H_WF1  = H_WSS  + (size_t)512 * HC;     // [10240,5120]
constexpr size_t H_WF2  = H_WF1  + (size_t)2 * HC * HC;  // [10240,5120]
constexpr size_t H_W1   = H_WF2  + (size_t)2 * HC * HC;  // [5120,640]
constexpr size_t H_W2   = H_W1   + (size_t)HC * 640;     // [640,640]
constexpr size_t HPOOL  = H_W2   + (size_t)640 * 640;

__device__ __half g_hpool[HPOOL];
__device__ float  g_fpool[6 * 32768 + 2 * 640 * 8];      // logits + vwd/vsd

constexpr size_t IOF_EIDX = 0;
constexpr size_t IOF_ROWP = IOF_EIDX + 65536;
constexpr size_t IOF_CNT  = IOF_ROWP + 4097;
__device__ int g_ipool[IOF_CNT + 4096];

// ---------------------------------------------------------------------------
// PTX helpers
// ---------------------------------------------------------------------------
__device__ __forceinline__ uint32_t smem_u32(const void* p) {
    uint32_t a;
    asm("{ .reg .u64 t; cvta.to.shared.u64 t, %1; cvt.u32.u64 %0, t; }" : "=r"(a) : "l"(p));
    return a;
}
__device__ __forceinline__ void cp16(uint32_t dst, const void* src) {
    asm volatile("cp.async.cg.shared.global [%0], [%1], 16;" :: "r"(dst), "l"(src));
}
__device__ __forceinline__ void ldsm4(uint32_t* r, uint32_t addr) {
    asm volatile("ldmatrix.sync.aligned.m8n8.x4.shared.b16 {%0,%1,%2,%3}, [%4];"
                 : "=r"(r[0]), "=r"(r[1]), "=r"(r[2]), "=r"(r[3]) : "r"(addr));
}
__device__ __forceinline__ void ldsm4t(uint32_t* r, uint32_t addr) {
    asm volatile("ldmatrix.sync.aligned.m8n8.x4.trans.shared.b16 {%0,%1,%2,%3}, [%4];"
                 : "=r"(r[0]), "=r"(r[1]), "=r"(r[2]), "=r"(r[3]) : "r"(addr));
}
__device__ __forceinline__ void mma16816(float* c, const uint32_t* a, uint32_t b0, uint32_t b1) {
    asm volatile("mma.sync.aligned.m16n8k16.row.col.f32.f16.f16.f32 "
                 "{%0,%1,%2,%3}, {%4,%5,%6,%7}, {%8,%9}, {%0,%1,%2,%3};"
                 : "+f"(c[0]), "+f"(c[1]), "+f"(c[2]), "+f"(c[3])
                 : "r"(a[0]), "r"(a[1]), "r"(a[2]), "r"(a[3]), "r"(b0), "r"(b1));
}

// ---------------------------------------------------------------------------
// fp16 GEMM: C[M,N] = A0[M,Kp0] @ B0[Kp0,N] (+ A1[M,Kp1] @ B1[Kp1,N])
// A row-major [M,Kp]; B K-major [Kp,N] loaded via ldmatrix.trans.
// tile 128x128, BK=64, 8 warps (2x4), 3-stage cp.async. M,N mult of 128.
// ---------------------------------------------------------------------------
#define STG 32768
#define GT_SMEM (3 * STG)

#define MODE_STORE  0
#define MODE_FUSION 1
#define MODE_RELU   2
#define MODE_FINAL  3

__global__ void __launch_bounds__(256, 2)
hgemm_kernel(const __half* __restrict__ A0, const __half* __restrict__ B0, int Kp0,
             const __half* __restrict__ A1, const __half* __restrict__ B1, int Kp1,
             void* __restrict__ Cv, int N, int mode,
             const float* __restrict__ bias,
             const void* __restrict__ aux0, const void* __restrict__ aux1)
{
    extern __shared__ char smem[];
    const uint32_t sb = smem_u32(smem);
    const int tid  = threadIdx.x;
    const int lane = tid & 31;
    const int warp = tid >> 5;
    const int wm = warp & 1, wn = warp >> 1;
    const int m0 = blockIdx.x * 128;
    const int n0 = blockIdx.y * 128;

    const int KB0 = Kp0 >> 6;
    const int KB1 = B1 ? (Kp1 >> 6) : 0;
    const int KB  = KB0 + KB1;

    auto load_tile = [&](int kb, int slot) {
        const __half* A; const __half* B; int Kp, kof;
        if (kb < KB0) { A = A0; B = B0; Kp = Kp0; kof = kb << 6; }
        else          { A = A1; B = B1; Kp = Kp1; kof = (kb - KB0) << 6; }
        const uint32_t sa  = sb + slot * STG;
        const uint32_t sbb = sa + 16384;
        // A tile [128 m][64 k], 128B rows, chunk swizzle
#pragma unroll
        for (int i = 0; i < 4; i++) {
            int idx = tid + i * 256;
            int row = idx >> 3, g = idx & 7;
            cp16(sa + row * 128 + ((g ^ (row & 7)) << 4),
                 A + (size_t)(m0 + row) * Kp + kof + g * 8);
        }
        // B tile [64 k][128 n], 256B rows (16 chunks), chunk c -> c ^ (k&7)
#pragma unroll
        for (int i = 0; i < 4; i++) {
            int idx = tid + i * 256;
            int k = idx >> 4, c = idx & 15;
            cp16(sbb + k * 256 + ((c ^ (k & 7)) << 4),
                 B + (size_t)(kof + k) * N + n0 + c * 8);
        }
        asm volatile("cp.async.commit_group;" ::: "memory");
    };

    float acc[4][4][4];
#pragma unroll
    for (int i = 0; i < 4; i++)
#pragma unroll
        for (int j = 0; j < 4; j++)
#pragma unroll
            for (int q = 0; q < 4; q++) acc[i][j][q] = 0.f;

    load_tile(0, 0);
    load_tile(1, 1);

    const int arow = lane & 15, apart = lane >> 4;
    const int bg = lane >> 3, bi = lane & 7;
    const int bk_off = ((bg >> 1) << 3) + bi;  // 0..15 within k16
    const int bn_off = (bg & 1) << 3;          // 0 or 8 within n16

    for (int kb = 0; kb < KB; kb++) {
        if (kb + 1 < KB) asm volatile("cp.async.wait_group 1;" ::: "memory");
        else             asm volatile("cp.async.wait_group 0;" ::: "memory");
        __syncthreads();
        if (kb + 2 < KB) load_tile(kb + 2, (kb + 2) % 3);

        const uint32_t sa  = sb + (kb % 3) * STG;
        const uint32_t sbb = sa + 16384;
#pragma unroll
        for (int ks = 0; ks < 4; ks++) {
            uint32_t a[4][4], b[2][4];
#pragma unroll
            for (int mf = 0; mf < 4; mf++) {
                int row = wm * 64 + mf * 16 + arow;
                ldsm4(a[mf], sa + row * 128 + ((((ks << 1) | apart) ^ (row & 7)) << 4));
            }
#pragma unroll
            for (int nfp = 0; nfp < 2; nfp++) {
                int k = ks * 16 + bk_off;
                int n = wn * 32 + nfp * 16 + bn_off;
                ldsm4t(b[nfp], sbb + k * 256 + ((((n >> 3)) ^ (k & 7)) << 4));
            }
#pragma unroll
            for (int mf = 0; mf < 4; mf++)
#pragma unroll
                for (int nf = 0; nf < 4; nf++)
                    mma16816(acc[mf][nf], a[mf], b[nf >> 1][nf & 1], b[nf >> 1][(nf & 1) + 2]);
        }
    }

    // Fused epilogue
    const __half* x0 = (const __half*)aux0;
    const __half* x1 = (const __half*)aux1;
    const float*  rf = (const float*)aux0;
#pragma unroll
    for (int mf = 0; mf < 4; mf++)
#pragma unroll
        for (int nf = 0; nf < 4; nf++)
#pragma unroll
            for (int h = 0; h < 2; h++) {
                int row = m0 + wm * 64 + mf * 16 + (lane >> 2) + h * 8;
                int col = n0 + wn * 32 + nf * 8 + ((lane & 3) << 1);
                float v0 = acc[mf][nf][h * 2], v1 = acc[mf][nf][h * 2 + 1];
                size_t off = (size_t)row * N + col;
                if (mode == MODE_STORE) {
                    *(__half2*)((__half*)Cv + off) = __floats2half2_rn(v0, v1);
                } else if (mode == MODE_FUSION) {
                    float b0v = bias[col], b1v = bias[col + 1];
                    float2 av = __half22float2(*(const __half2*)(x0 + off));
                    float2 bv = __half22float2(*(const __half2*)(x1 + off));
                    float z0 = 1.f / (1.f + expf(-(v0 + b0v)));
                    float z1 = 1.f / (1.f + expf(-(v1 + b1v)));
                    *(__half2*)((__half*)Cv + off) =
                        __floats2half2_rn(z0 * av.x + (1.f - z0) * bv.x,
                                          z1 * av.y + (1.f - z1) * bv.y);
                } else if (mode == MODE_RELU) {
                    *(__half2*)((__half*)Cv + off) =
                        __floats2half2_rn(fmaxf(v0 + bias[col], 0.f),
                                          fmaxf(v1 + bias[col + 1], 0.f));
                } else {
                    *(float2*)((float*)Cv + off) =
                        make_float2(v0 + bias[col] + rf[off],
                                    v1 + bias[col + 1] + rf[off + 1]);
                }
            }
}

// ---------------------------------------------------------------------------
// Streaming fp32 -> fp16 convert, [K,N] -> [Kp,N] with zero-pad rows.
// grid (Kp, ysplit), 256 threads, float4 vectorized.
// ---------------------------------------------------------------------------
__global__ void convB_kernel(const float* __restrict__ in, __half* __restrict__ out,
                             int K, int N)
{
    int r = blockIdx.x;
    const float4* src = (const float4*)(in + (size_t)r * N);
    __half2* dst = (__half2*)(out + (size_t)r * N);
    bool zero = (r >= K);
    int n4 = N >> 2;
    for (int c = threadIdx.x + blockIdx.y * blockDim.x; c < n4; c += blockDim.x * gridDim.y) {
        float4 v = zero ? make_float4(0.f, 0.f, 0.f, 0.f) : src[c];
        dst[2 * c]     = __floats2half2_rn(v.x, v.y);
        dst[2 * c + 1] = __floats2half2_rn(v.z, v.w);
    }
}

// scalar convert with col pad (for Hw rows 0..4095, 300 -> 320)
__global__ void convert_pad_kernel(const float* __restrict__ in, __half* __restrict__ out,
                                   int K, int Kp, int total)
{
    int i = blockIdx.x * blockDim.x + threadIdx.x;
    if (i >= total) return;
    int r = i / Kp, c = i % Kp;
    out[i] = __float2half(c < K ? in[(size_t)r * K + c] : 0.f);
}

// ---------------------------------------------------------------------------
// v[k][h] = sum_c W[k, h*CH+c] * a[h,c]      (W: [Kdim, HC] fp32)
// ---------------------------------------------------------------------------
__global__ void vdot_kernel(const float* __restrict__ W, const float* __restrict__ a,
                            float* __restrict__ v)
{
    int k = blockIdx.x;
    int h = threadIdx.x >> 5, lane = threadIdx.x & 31;
    const float* wr = W + (size_t)k * HC + h * CH;
    const float* ar = a + h * CH;
    float s = 0.f;
#pragma unroll
    for (int i = lane; i < CH; i += 32) s += wr[i] * ar[i];
#pragma unroll
    for (int o = 16; o; o >>= 1) s += __shfl_xor_sync(0xffffffffu, s, o);
    if (lane == 0) v[k * H_HEADS + h] = s;
}

// al[n][h] = sum_k X[n,k] * v[k,h]            (X: [Nn,640] fp32)
__global__ void aldot_kernel(const float* __restrict__ X, const float* __restrict__ v,
                             float* __restrict__ al)
{
    __shared__ float xs[640];
    int n = blockIdx.x;
    for (int i = threadIdx.x; i < 640; i += blockDim.x) xs[i] = X[(size_t)n * 640 + i];
    __syncthreads();
    int h = threadIdx.x >> 5, lane = threadIdx.x & 31;
    float s = 0.f;
    for (int i = lane; i < 640; i += 32) s += xs[i] * v[i * H_HEADS + h];
#pragma unroll
    for (int o = 16; o; o >>= 1) s += __shfl_xor_sync(0xffffffffu, s, o);
    if (lane == 0) al[n * H_HEADS + h] = s;
}

// ---------------------------------------------------------------------------
// Attention logits from half tables
// ---------------------------------------------------------------------------
__global__ void node_alpha_kernel(const __half* __restrict__ h, const float* __restrict__ a,
                                  float* __restrict__ al)
{
    int node = blockIdx.x;
    int w = threadIdx.x >> 5, lane = threadIdx.x & 31;
    const uint2* hv = (const uint2*)(h + (size_t)node * HC + w * CH);
    const float4* av = (const float4*)(a + w * CH);
    float s = 0.f;
#pragma unroll
    for (int i = 0; i < 5; i++) {
        uint2 raw = hv[lane + 32 * i];
        float4 y = av[lane + 32 * i];
        float2 f01 = __half22float2(*(__half2*)&raw.x);
        float2 f23 = __half22float2(*(__half2*)&raw.y);
        s += f01.x * y.x + f01.y * y.y + f23.x * y.z + f23.y * y.w;
    }
#pragma unroll
    for (int o = 16; o; o >>= 1) s += __shfl_xor_sync(0xffffffffu, s, o);
    if (lane == 0) al[node * H_HEADS + w] = s;
}

// ---------------------------------------------------------------------------
// CSR build
// ---------------------------------------------------------------------------
__global__ void count_kernel(const int* __restrict__ dst, int* __restrict__ cnt, int E)
{
    int e = blockIdx.x * blockDim.x + threadIdx.x;
    if (e < E) atomicAdd(&cnt[min(dst[e], NS - 1)], 1);
}

__global__ void scan_kernel(const int* __restrict__ cnt, int* __restrict__ rowptr)
{
    __shared__ int sd[1024];
    int t = threadIdx.x, base = t * 4;
    int a0 = cnt[base], a1 = cnt[base+1], a2 = cnt[base+2], a3 = cnt[base+3];
    int s = a0 + a1 + a2 + a3;
    sd[t] = s;
    __syncthreads();
    for (int off = 1; off < 1024; off <<= 1) {
        int v = (t >= off) ? sd[t - off] : 0;
        __syncthreads();
        sd[t] += v;
        __syncthreads();
    }
    int ex = sd[t] - s;
    rowptr[base] = ex; rowptr[base+1] = ex+a0; rowptr[base+2] = ex+a0+a1; rowptr[base+3] = ex+a0+a1+a2;
    if (t == 1023) rowptr[4096] = sd[1023];
}

__global__ void scatter_kernel(const int* __restrict__ dst, const int* __restrict__ rowptr,
                               int* __restrict__ cur, int* __restrict__ eidx, int E)
{
    int e = blockIdx.x * blockDim.x + threadIdx.x;
    if (e < E) {
        int d = min(dst[e], NS - 1);
        eidx[rowptr[d] + atomicAdd(&cur[d], 1)] = e;
    }
}

// ---------------------------------------------------------------------------
// Fused GAT
// ---------------------------------------------------------------------------
__device__ __forceinline__ float lrelu(float x) { return x > 0.f ? x : NEG_SLOPE * x; }
__device__ __forceinline__ float eluf(float x)  { return x > 0.f ? x : expf(x) - 1.f; }
#define CHUNK 128

__global__ void gat_kernel(const int* __restrict__ eidx, const int* __restrict__ rowptr,
                           const int* __restrict__ esrc,
                           const float* __restrict__ al_s, const float* __restrict__ al_d,
                           const __half* __restrict__ hsrc, const float* __restrict__ bias,
                           __half* __restrict__ U, int n_src_m1)
{
    const int d = blockIdx.x;
    const int tid = threadIdx.x;
    const int w = tid >> 5, lane = tid & 31;

    __shared__ float ald8[H_HEADS];
    __shared__ float alpha_s[CHUNK * H_HEADS];
    __shared__ int   s_idx[CHUNK];

    const int r0 = rowptr[d];
    const int deg = rowptr[d + 1] - r0;

    if (tid < H_HEADS) ald8[tid] = al_d[d * H_HEADS + tid];
    __syncthreads();

    float mx = -3.4e38f;
    for (int e = lane; e < deg; e += 32) {
        int s = min(esrc[eidx[r0 + e]], n_src_m1);
        mx = fmaxf(mx, lrelu(al_s[s * H_HEADS + w] + ald8[w]));
    }
#pragma unroll
    for (int o = 16; o; o >>= 1) mx = fmaxf(mx, __shfl_xor_sync(0xffffffffu, mx, o));
    float dn = 0.f;
    for (int e = lane; e < deg; e += 32) {
        int s = min(esrc[eidx[r0 + e]], n_src_m1);
        dn += expf(lrelu(al_s[s * H_HEADS + w] + ald8[w]) - mx);
    }
#pragma unroll
    for (int o = 16; o; o >>= 1) dn += __shfl_xor_sync(0xffffffffu, dn, o);
    const float invden = 1.f / (dn + 1e-16f);

    float4 acc[5];
#pragma unroll
    for (int j = 0; j < 5; j++) acc[j] = make_float4(0.f, 0.f, 0.f, 0.f);
    int hj[5];
#pragma unroll
    for (int j = 0; j < 5; j++) hj[j] = (tid * 4 + j * 1024) / CH;

    for (int cs = 0; cs < deg; cs += CHUNK) {
        int cnt = min(CHUNK, deg - cs);
        __syncthreads();
        for (int e = lane; e < cnt; e += 32) {
            int s = min(esrc[eidx[r0 + cs + e]], n_src_m1);
            alpha_s[e * H_HEADS + w] = expf(lrelu(al_s[s * H_HEADS + w] + ald8[w]) - mx) * invden;
            if (w == 0) s_idx[e] = s;
        }
        __syncthreads();
        for (int e = 0; e < cnt; e++) {
            int s = s_idx[e];
            const uint2* hv = (const uint2*)(hsrc + (size_t)s * HC);
#pragma unroll
            for (int j = 0; j < 5; j++) {
                float a = alpha_s[e * H_HEADS + hj[j]];
                uint2 raw = hv[tid + j * 256];
                float2 f01 = __half22float2(*(__half2*)&raw.x);
                float2 f23 = __half22float2(*(__half2*)&raw.y);
                acc[j].x += a * f01.x; acc[j].y += a * f01.y;
                acc[j].z += a * f23.x; acc[j].w += a * f23.y;
            }
        }
    }

    __half2* Urow = (__half2*)(U + (size_t)d * HC);
    const float4* bv = (const float4*)bias;
#pragma unroll
    for (int j = 0; j < 5; j++) {
        float4 b = bv[tid + j * 256];
        int p = (tid + j * 256) * 2;
        Urow[p]     = __floats2half2_rn(eluf(acc[j].x + b.x), eluf(acc[j].y + b.y));
        Urow[p + 1] = __floats2half2_rn(eluf(acc[j].z + b.z), eluf(acc[j].w + b.w));
    }
}

// ---------------------------------------------------------------------------
// Host side
// ---------------------------------------------------------------------------
static void run_hgemm(const __half* A0, const __half* B0, int Kp0,
                      const __half* A1, const __half* B1, int Kp1,
                      void* C, int M, int N, int mode,
                      const float* bias, const void* aux0, const void* aux1)
{
    cudaFuncSetAttribute(hgemm_kernel, cudaFuncAttributeMaxDynamicSharedMemorySize, GT_SMEM);
    dim3 grid(M / 128, N / 128);
    hgemm_kernel<<<grid, 256, GT_SMEM>>>(A0, B0, Kp0, A1, B1, Kp1, C, N, mode, bias, aux0, aux1);
}

static void run_convB(const float* in, __half* out, int K, int Kp, int N)
{
    convB_kernel<<<dim3(Kp, 8), 256>>>(in, out, K, N);
}

static void run_gat(const int* edges, int E,
                    const float* al_s, const float* al_d,
                    const __half* hsrc, const float* bias,
                    __half* U, int n_src, int* ip)
{
    const int* src = edges;
    const int* dst = edges + E;
    int* eidx = ip + IOF_EIDX;
    int* rowp = ip + IOF_ROWP;
    int* cnt  = ip + IOF_CNT;
    cudaMemsetAsync(cnt, 0, 4096 * sizeof(int));
    count_kernel<<<(E + 255) / 256, 256>>>(dst, cnt, E);
    scan_kernel<<<1, 1024>>>(cnt, rowp);
    cudaMemsetAsync(cnt, 0, 4096 * sizeof(int));
    scatter_kernel<<<(E + 255) / 256, 256>>>(dst, rowp, cnt, eidx, E);
    gat_kernel<<<NS, 256>>>(eidx, rowp, src, al_s, al_d, hsrc, bias, U, n_src - 1);
}

extern "C" void kernel_launch(void* const* d_in, const int* in_sizes, int n_in,
                              void* d_out, int out_size)
{
    const float* Hs     = (const float*)d_in[0];
    const float* Hw     = (const float*)d_in[1];
    const float* HSc    = (const float*)d_in[2];
    const int*   w2s    = (const int*)d_in[3];
    const int*   s2s    = (const int*)d_in[4];
    const int*   S2s    = (const int*)d_in[5];
    const float* Ww_src = (const float*)d_in[6];
    const float* Ww_dst = (const float*)d_in[7];
    const float* aw_src = (const float*)d_in[8];
    const float* aw_dst = (const float*)d_in[9];
    const float* bw     = (const float*)d_in[10];
    const float* Ws     = (const float*)d_in[11];
    const float* as_src = (const float*)d_in[12];
    const float* as_dst = (const float*)d_in[13];
    const float* bs     = (const float*)d_in[14];
    const float* WS_src = (const float*)d_in[15];
    const float* WS_dst = (const float*)d_in[16];
    const float* aS_src = (const float*)d_in[17];
    const float* aS_dst = (const float*)d_in[18];
    const float* bS     = (const float*)d_in[19];
    const float* Wf1    = (const float*)d_in[20];
    const float* bf1    = (const float*)d_in[21];
    const float* Wf2    = (const float*)d_in[22];
    const float* bf2    = (const float*)d_in[23];
    const float* W1     = (const float*)d_in[24];
    const float* b1     = (const float*)d_in[25];
    const float* W2     = (const float*)d_in[26];
    const float* b2     = (const float*)d_in[27];
    float* out = (float*)d_out;

    const int E_w = in_sizes[3] / 2;
    const int E_s = in_sizes[4] / 2;
    const int E_S = in_sizes[5] / 2;

    __half* hp = nullptr; float* fp = nullptr; int* ip = nullptr;
    cudaGetSymbolAddress((void**)&hp, g_hpool);
    cudaGetSymbolAddress((void**)&fp, g_fpool);
    cudaGetSymbolAddress((void**)&ip, g_ipool);

    __half* hsw  = hp + H_HSW;
    __half* hss  = hp + H_HSS;
    __half* hSec = hp + H_HSEC;
    __half* Uw   = hp + H_UW;
    __half* Us   = hp + H_US;
    __half* USc  = hp + H_USC;
    __half* U1   = hp + H_U1;
    __half* U2   = hp + H_U2;
    __half* ffnh = hp + H_FFNH;
    __half* ahw  = hp + H_AHW;
    __half* ahs  = hp + H_AHS;
    __half* ahsc = hp + H_AHSC;
    __half* wws  = hp + H_WWS;
    __half* wsp  = hp + H_WS;
    __half* wss  = hp + H_WSS;
    __half* wf1  = hp + H_WF1;
    __half* wf2  = hp + H_WF2;
    __half* w1c  = hp + H_W1;
    __half* w2c  = hp + H_W2;

    float* alws = fp;
    float* alwd = alws + 32768;
    float* alss = alwd + 32768;
    float* alsd = alss + 32768;
    float* alxs = alsd + 32768;
    float* alxd = alxs + 32768;
    float* vwd  = alxd + 32768;          // [640,8]
    float* vsd  = vwd + 640 * 8;         // [640,8]

    // ---- activation converts (fp16)
    {
        int total = NS * 320;
        convert_pad_kernel<<<(total + 255) / 256, 256>>>(Hw, ahw, 300, 320, total);
    }
    run_convB(Hs,  ahs,  NS,   NS,   640);
    run_convB(HSc, ahsc, NSEC, NSEC, 512);

    // ---- weight converts, native [K,N] layout (no transpose)
    run_convB(Ww_src, wws, 300, 320, HC);
    run_convB(Ws,     wsp, 640, 640, HC);
    run_convB(WS_src, wss, 512, 512, HC);
    run_convB(Wf1, wf1, 2 * HC, 2 * HC, HC);
    run_convB(Wf2, wf2, 2 * HC, 2 * HC, HC);
    run_convB(W1,  w1c, HC,  HC,  640);
    run_convB(W2,  w2c, 640, 640, 640);

    // ---- dst-logit shortcut: al_d = Hs @ (W_dst @ a_dst)   (fp32, exact math)
    vdot_kernel<<<640, 256>>>(Ww_dst, aw_dst, vwd);
    vdot_kernel<<<640, 256>>>(WS_dst, aS_dst, vsd);
    aldot_kernel<<<NS, 256>>>(Hs, vwd, alwd);
    aldot_kernel<<<NS, 256>>>(Hs, vsd, alxd);

    // ---- projections (src tables only; dst tables eliminated)
    run_hgemm(ahw,  wws, 320, 0, 0, 0, hsw,  NS,   HC, MODE_STORE, 0, 0, 0);
    run_hgemm(ahs,  wsp, 640, 0, 0, 0, hss,  NS,   HC, MODE_STORE, 0, 0, 0);
    run_hgemm(ahsc, wss, 512, 0, 0, 0, hSec, NSEC, HC, MODE_STORE, 0, 0, 0);

    // ---- src attention logits
    node_alpha_kernel<<<NS,   256>>>(hsw,  aw_src, alws);
    node_alpha_kernel<<<NS,   256>>>(hss,  as_src, alss);
    node_alpha_kernel<<<NS,   256>>>(hss,  as_dst, alsd);
    node_alpha_kernel<<<NSEC, 256>>>(hSec, aS_src, alxs);

    // ---- GATs
    run_gat(w2s, E_w, alws, alwd, hsw,  bw, Uw,  NS,   ip);
    run_gat(s2s, E_s, alss, alsd, hss,  bs, Us,  NS,   ip);
    run_gat(S2s, E_S, alxs, alxd, hSec, bS, USc, NSEC, ip);

    // ---- fusion gates (concat = two contiguous K-row segments of wf1/wf2)
    run_hgemm(Uw, wf1, HC, Us,  wf1 + (size_t)HC * HC, HC, U1, NS, HC, MODE_FUSION, bf1, Uw, Us);
    run_hgemm(U1, wf2, HC, USc, wf2 + (size_t)HC * HC, HC, U2, NS, HC, MODE_FUSION, bf2, U1, USc);

    // ---- FFN + residual
    run_hgemm(U2,   w1c, HC,  0, 0, 0, ffnh, NS, 640, MODE_RELU,  b1, 0,  0);
    run_hgemm(ffnh, w2c, 640, 0, 0, 0, out,  NS, 640, MODE_FINAL, b2, Hs, 0);
}